// round 8
// baseline (speedup 1.0000x reference)
#include <cuda_runtime.h>
#include <cstdint>

#define FULL_MASK 0xFFFFFFFFu
#define KPL 8                 // timesteps per lane
#define SEG (32 * KPL)        // 256 timesteps per warp-segment
#define NW  8                 // warps per block (one block = one row)
#define PAD_W 9               // padded smem words per lane (conflict-free)

// fast sigmoid via MUFU; rel err ~1e-6, far under 1e-3 tol.
__device__ __forceinline__ float fsigmoid(float x) {
    return __fdividef(1.0f, 1.0f + __expf(-x));
}

// Precomputed per-timestep lambda and gamma (written by prep_kernel).
__device__ __align__(16) float g_lam_tab[16384];
__device__ float g_gamma_c;

__global__ void prep_kernel(const float* __restrict__ raw_gamma,
                            const float* __restrict__ raw_lambd,
                            const int*   __restrict__ p_start,
                            int T)
{
    int t = blockIdx.x * blockDim.x + threadIdx.x;
    if (t == 0) {
        g_gamma_c = 0.98f + 0.02f * fsigmoid(raw_gamma[0]);  // 0.99+0.01*(2s-1)
    }
    int s0 = p_start ? p_start[0] : 0;
    if (t < T) {
        g_lam_tab[t] = fmaf(0.1f, fsigmoid(raw_lambd[s0 + t]), 0.9f);  // 0.9+0.1s
    }
}

// One BLOCK per batch row; 8 warps process 8 segments of the row in parallel.
// Backward affine scan: x_t = A_t*x_{t+1} + B_t, A_t = g*(1-d_t)*l_t.
// Parallel decomposition: each warp composes its segment's map concurrently
// (loads overlap chip-wide), then a tiny 8-map block combine distributes
// carries, then all warps expand & store concurrently.
__global__ __launch_bounds__(NW * 32)
void td_scan_kernel(const float* __restrict__ values,   // [B, T+1]
                    const float* __restrict__ rewards,  // [B, T]
                    const float* __restrict__ dones,    // [B, T]
                    float* __restrict__ out_lam,        // [B, T+1]
                    float* __restrict__ out_sum,        // [B, T]
                    int B, int T)
{
    __shared__ float vstage[NW][32 * PAD_W];   // per-warp transpose staging
    __shared__ float wA[NW], wBl[NW], wBs[NW]; // per-warp composed maps

    const int lane = threadIdx.x & 31;
    const int wid  = threadIdx.x >> 5;
    const int row  = blockIdx.x;
    if (row >= B) return;

    const float g = g_gamma_c;
    float* st = vstage[wid];

    const float* vrow = values  + (size_t)row * (size_t)(T + 1);
    const float* rrow = rewards + (size_t)row * (size_t)T;
    const float* drow = dones   + (size_t)row * (size_t)T;
    float* lrow = out_lam + (size_t)row * (size_t)(T + 1);
    float* srow = out_sum + (size_t)row * (size_t)T;

    const float vlast = vrow[T];
    if (threadIdx.x == 0) lrow[T] = vlast;

    float c_lam = vlast;   // block-level carry (state at right edge of chunk)
    float c_sum = 0.0f;

    const int nseg   = (T + SEG - 1) / SEG;
    const int nchunk = (nseg + NW - 1) / NW;
    const bool tvec  = ((T & 3) == 0);   // row bases 16B-aligned

    for (int c = nchunk - 1; c >= 0; --c) {
        const int seg  = c * NW + wid;
        const int segb = seg * SEG;
        const int base = segb + lane * KPL;
        const bool active = (seg < nseg);
        const bool full   = active && tvec && (segb + SEG <= T);

        float A[KPL], Bl[KPL], Bs[KPL];

        if (full) {
            // rewards/dones: LDG.128, lane-contiguous
            float4 ra = *((const float4*)(rrow + base));
            float4 rb = *((const float4*)(rrow + base) + 1);
            float4 da = *((const float4*)(drow + base));
            float4 db = *((const float4*)(drow + base) + 1);

            // lambda: L1-hot shared table, LDG.128
            float4 la = *((const float4*)(g_lam_tab + base));
            float4 lb = *((const float4*)(g_lam_tab + base) + 1);

            // values window [segb+1 .. segb+SEG]: coalesced scalar loads,
            // transpose through padded smem to per-lane contiguous regs.
            float vt[8];
            const float* vp = vrow + segb + 1;
            #pragma unroll
            for (int k = 0; k < 8; k++) vt[k] = __ldg(vp + k * 32 + lane);
            #pragma unroll
            for (int k = 0; k < 8; k++) {
                int i = k * 32 + lane;
                st[(i >> 3) * PAD_W + (i & 7)] = vt[k];
            }
            __syncwarp();
            float vn[KPL];
            #pragma unroll
            for (int j = 0; j < KPL; j++) vn[j] = st[lane * PAD_W + j];
            __syncwarp();

            float r[KPL] = {ra.x, ra.y, ra.z, ra.w, rb.x, rb.y, rb.z, rb.w};
            float d[KPL] = {da.x, da.y, da.z, da.w, db.x, db.y, db.z, db.w};
            float l[KPL] = {la.x, la.y, la.z, la.w, lb.x, lb.y, lb.z, lb.w};

            #pragma unroll
            for (int j = 0; j < KPL; j++) {
                float cont = g - g * d[j];               // gamma*(1-done)
                A[j]  = cont * l[j];
                Bl[j] = fmaf(cont - A[j], vn[j], r[j]);  // cont*(1-l)*vn + r
                Bs[j] = r[j];
            }
        } else if (active) {
            #pragma unroll
            for (int j = 0; j < KPL; j++) {
                int t = base + j;
                if (t < T) {
                    float r  = rrow[t];
                    float d  = drow[t];
                    float vn = vrow[t + 1];
                    float l  = g_lam_tab[t];
                    float cont = g - g * d;
                    A[j]  = cont * l;
                    Bl[j] = fmaf(cont - A[j], vn, r);
                    Bs[j] = r;
                } else {
                    A[j] = 1.0f; Bl[j] = 0.0f; Bs[j] = 0.0f;
                }
            }
        } else {
            #pragma unroll
            for (int j = 0; j < KPL; j++) { A[j] = 1.0f; Bl[j] = 0.0f; Bs[j] = 0.0f; }
        }

        // Local composition: S = m_0 ∘ ... ∘ m_{KPL-1}
        float SA = A[KPL - 1], SBl = Bl[KPL - 1], SBs = Bs[KPL - 1];
        #pragma unroll
        for (int j = KPL - 2; j >= 0; --j) {
            SBl = fmaf(A[j], SBl, Bl[j]);
            SBs = fmaf(A[j], SBs, Bs[j]);
            SA  = A[j] * SA;
        }

        // Warp inclusive suffix scan (lane i = comp of lanes i..31).
        #pragma unroll
        for (int len = 1; len < 32; len <<= 1) {
            float Ao  = __shfl_down_sync(FULL_MASK, SA,  len);
            float Blo = __shfl_down_sync(FULL_MASK, SBl, len);
            float Bso = __shfl_down_sync(FULL_MASK, SBs, len);
            if (lane + len < 32) {
                SBl = fmaf(SA, Blo, SBl);
                SBs = fmaf(SA, Bso, SBs);
                SA  = SA * Ao;
            }
        }

        // Publish whole-warp map (lane 0's scanned value).
        if (lane == 0) { wA[wid] = SA; wBl[wid] = SBl; wBs[wid] = SBs; }
        __syncthreads();

        // Block combine (redundant in every thread): walk maps right-to-left,
        // snapshotting the carry that enters this warp's segment.
        float cl = c_lam, cs = c_sum;
        float inl = c_lam, ins = c_sum;
        #pragma unroll
        for (int w = NW - 1; w >= 0; --w) {
            if (w == wid) { inl = cl; ins = cs; }
            cl = fmaf(wA[w], cl, wBl[w]);
            cs = fmaf(wA[w], cs, wBs[w]);
        }
        c_lam = cl;   // carry after the whole chunk (for next loop iter)
        c_sum = cs;

        // Per-lane incoming state: maps of lanes lane+1..31 applied to (inl,ins).
        float nA  = __shfl_down_sync(FULL_MASK, SA,  1);
        float nBl = __shfl_down_sync(FULL_MASK, SBl, 1);
        float nBs = __shfl_down_sync(FULL_MASK, SBs, 1);
        float xl = (lane == 31) ? inl : fmaf(nA, inl, nBl);
        float xs = (lane == 31) ? ins : fmaf(nA, ins, nBs);

        // Local expansion.
        float outl[KPL], outs[KPL];
        #pragma unroll
        for (int j = KPL - 1; j >= 0; --j) {
            xl = fmaf(A[j], xl, Bl[j]);
            xs = fmaf(A[j], xs, Bs[j]);
            outl[j] = xl;
            outs[j] = xs;
        }

        if (full) {
            // sum rows aligned -> streaming STG.128
            float4* s4 = (float4*)(srow + base);
            __stcs(s4,     make_float4(outs[0], outs[1], outs[2], outs[3]));
            __stcs(s4 + 1, make_float4(outs[4], outs[5], outs[6], outs[7]));

            // lam rows misaligned -> transpose via smem, coalesced STG.32
            #pragma unroll
            for (int j = 0; j < KPL; j++) st[lane * PAD_W + j] = outl[j];
            __syncwarp();
            float* lp = lrow + segb;
            #pragma unroll
            for (int k = 0; k < 8; k++) {
                int i = k * 32 + lane;
                __stcs(lp + i, st[(i >> 3) * PAD_W + (i & 7)]);
            }
        } else if (active) {
            #pragma unroll
            for (int j = 0; j < KPL; j++) {
                if (base + j < T) { lrow[base + j] = outl[j]; srow[base + j] = outs[j]; }
            }
        }

        __syncthreads();   // wA/wBl/wBs & staging safe for next chunk
    }
}

extern "C" void kernel_launch(void* const* d_in, const int* in_sizes, int n_in,
                              void* d_out, int out_size)
{
    const float* values    = (const float*)d_in[0];
    const float* rewards   = (const float*)d_in[1];
    const float* dones     = (const float*)d_in[2];
    const float* raw_gamma = (const float*)d_in[3];
    const float* raw_lambd = (const float*)d_in[4];
    const int*   p_start   = (n_in > 5) ? (const int*)d_in[5] : nullptr;

    const int T = in_sizes[4];
    const int B = in_sizes[1] / T;

    float* out_lam = (float*)d_out;                       // B*(T+1)
    float* out_sum = (float*)d_out + (size_t)B * (T + 1); // B*T

    prep_kernel<<<(T + 255) / 256, 256>>>(raw_gamma, raw_lambd, p_start, T);

    td_scan_kernel<<<B, NW * 32>>>(
        values, rewards, dones, out_lam, out_sum, B, T);
}

// round 9
// speedup vs baseline: 1.2043x; 1.2043x over previous
#include <cuda_runtime.h>
#include <cstdint>

#define FULL_MASK 0xFFFFFFFFu
#define KPL 8                 // timesteps per lane
#define SEG (32 * KPL)        // 256 timesteps per warp-segment
#define WPB 2                 // warps per block
#define PAD_W 9               // padded smem words per lane (conflict-free)

// fast sigmoid via MUFU (EX2 + RCP); rel err ~1e-6, far under 1e-3 tol.
__device__ __forceinline__ float fsigmoid(float x) {
    return __fdividef(1.0f, 1.0f + __expf(-x));
}

// One warp per batch row. Backward affine scan:
//   x_t = A_t * x_{t+1} + B_t,   A_t = g*(1-d_t)*l_t  (shared by both recurrences)
// Single launch: gamma/lambda sigmoids computed inline on MUFU (idle pipe),
// raw_lambd is an 8KB L1-hot table shared by every warp.
__global__ __launch_bounds__(WPB * 32)
void td_scan_kernel(const float* __restrict__ values,    // [B, T+1]
                    const float* __restrict__ rewards,   // [B, T]
                    const float* __restrict__ dones,     // [B, T]
                    const float* __restrict__ raw_gamma, // [1]
                    const float* __restrict__ raw_lambd, // [>=T]
                    const int*   __restrict__ p_start,   // [1] or null
                    float* __restrict__ out_lam,         // [B, T+1]
                    float* __restrict__ out_sum,         // [B, T]
                    int B, int T)
{
    __shared__ float stage[WPB][32 * PAD_W];

    const int lane = threadIdx.x & 31;
    const int wid  = threadIdx.x >> 5;
    const int row  = blockIdx.x * WPB + wid;
    if (row >= B) return;

    const int s0 = p_start ? __ldg(p_start) : 0;
    // gamma = 0.99 + 0.01*(2*sig-1) = 0.98 + 0.02*sigmoid  (L1-hot broadcast)
    const float g = 0.98f + 0.02f * fsigmoid(__ldg(raw_gamma));
    const bool lam_vec = ((s0 & 3) == 0);   // vectorizable lambda loads?

    float* st = stage[wid];
    const float* vrow = values  + (size_t)row * (size_t)(T + 1);
    const float* rrow = rewards + (size_t)row * (size_t)T;
    const float* drow = dones   + (size_t)row * (size_t)T;
    float* lrow = out_lam + (size_t)row * (size_t)(T + 1);
    float* srow = out_sum + (size_t)row * (size_t)T;

    const float vlast = vrow[T];
    if (lane == 0) lrow[T] = vlast;

    float c_lam = vlast;
    float c_sum = 0.0f;

    const int nseg = (T + SEG - 1) / SEG;

    for (int s = nseg - 1; s >= 0; --s) {
        const int segb = s * SEG;
        const int base = segb + lane * KPL;
        const bool full = (segb + SEG <= T);

        float A[KPL], Bl[KPL], Bs[KPL];

        if (full) {
            // rewards/dones: LDG.128 (rows 16B-aligned at base)
            float4 ra = *((const float4*)(rrow + base));
            float4 rb = *((const float4*)(rrow + base) + 1);
            float4 da = *((const float4*)(drow + base));
            float4 db = *((const float4*)(drow + base) + 1);

            // raw lambda: L1-hot shared table
            float xl_[KPL];
            if (lam_vec) {
                float4 xa = *((const float4*)(raw_lambd + s0 + base));
                float4 xb = *((const float4*)(raw_lambd + s0 + base) + 1);
                xl_[0]=xa.x; xl_[1]=xa.y; xl_[2]=xa.z; xl_[3]=xa.w;
                xl_[4]=xb.x; xl_[5]=xb.y; xl_[6]=xb.z; xl_[7]=xb.w;
            } else {
                #pragma unroll
                for (int j = 0; j < KPL; j++) xl_[j] = __ldg(raw_lambd + s0 + base + j);
            }

            // values window [segb+1 .. segb+SEG]: coalesced scalar loads,
            // transpose through padded smem to per-lane contiguous regs.
            float vt[8];
            const float* vp = vrow + segb + 1;
            #pragma unroll
            for (int k = 0; k < 8; k++) vt[k] = __ldg(vp + k * 32 + lane);
            #pragma unroll
            for (int k = 0; k < 8; k++) {
                int i = k * 32 + lane;
                st[(i >> 3) * PAD_W + (i & 7)] = vt[k];
            }
            __syncwarp();
            float vn[KPL];
            #pragma unroll
            for (int j = 0; j < KPL; j++) vn[j] = st[lane * PAD_W + j];
            __syncwarp();

            float r[KPL] = {ra.x, ra.y, ra.z, ra.w, rb.x, rb.y, rb.z, rb.w};
            float d[KPL] = {da.x, da.y, da.z, da.w, db.x, db.y, db.z, db.w};

            #pragma unroll
            for (int j = 0; j < KPL; j++) {
                // lambda = 0.95 + 0.05*(2*sig-1) = 0.9 + 0.1*sigmoid (MUFU)
                float l = fmaf(0.1f, fsigmoid(xl_[j]), 0.9f);
                float cont = g - g * d[j];               // gamma*(1-done)
                A[j]  = cont * l;
                Bl[j] = fmaf(cont - A[j], vn[j], r[j]);  // cont*(1-l)*vn + r
                Bs[j] = r[j];
            }
        } else {
            #pragma unroll
            for (int j = 0; j < KPL; j++) {
                int t = base + j;
                if (t < T) {
                    float r  = rrow[t];
                    float d  = drow[t];
                    float vn = vrow[t + 1];
                    float l  = fmaf(0.1f, fsigmoid(__ldg(raw_lambd + s0 + t)), 0.9f);
                    float cont = g - g * d;
                    A[j]  = cont * l;
                    Bl[j] = fmaf(cont - A[j], vn, r);
                    Bs[j] = r;
                } else {
                    A[j] = 1.0f; Bl[j] = 0.0f; Bs[j] = 0.0f;
                }
            }
        }

        // Local composition: S = m_0 ∘ ... ∘ m_{KPL-1}
        float SA = A[KPL - 1], SBl = Bl[KPL - 1], SBs = Bs[KPL - 1];
        #pragma unroll
        for (int j = KPL - 2; j >= 0; --j) {
            SBl = fmaf(A[j], SBl, Bl[j]);
            SBs = fmaf(A[j], SBs, Bs[j]);
            SA  = A[j] * SA;
        }

        // Warp inclusive suffix scan of lane maps.
        #pragma unroll
        for (int len = 1; len < 32; len <<= 1) {
            float Ao  = __shfl_down_sync(FULL_MASK, SA,  len);
            float Blo = __shfl_down_sync(FULL_MASK, SBl, len);
            float Bso = __shfl_down_sync(FULL_MASK, SBs, len);
            if (lane + len < 32) {
                SBl = fmaf(SA, Blo, SBl);
                SBs = fmaf(SA, Bso, SBs);
                SA  = SA * Ao;
            }
        }

        // Incoming state for this lane.
        float nA  = __shfl_down_sync(FULL_MASK, SA,  1);
        float nBl = __shfl_down_sync(FULL_MASK, SBl, 1);
        float nBs = __shfl_down_sync(FULL_MASK, SBs, 1);
        float xl = (lane == 31) ? c_lam : fmaf(nA, c_lam, nBl);
        float xs = (lane == 31) ? c_sum : fmaf(nA, c_sum, nBs);

        // Local expansion.
        float outl[KPL], outs[KPL];
        #pragma unroll
        for (int j = KPL - 1; j >= 0; --j) {
            xl = fmaf(A[j], xl, Bl[j]);
            xs = fmaf(A[j], xs, Bs[j]);
            outl[j] = xl;
            outs[j] = xs;
        }

        if (full) {
            // sum rows aligned -> streaming STG.128
            float4* s4 = (float4*)(srow + base);
            __stcs(s4,     make_float4(outs[0], outs[1], outs[2], outs[3]));
            __stcs(s4 + 1, make_float4(outs[4], outs[5], outs[6], outs[7]));

            // lam rows misaligned -> transpose via smem, coalesced STG.32
            #pragma unroll
            for (int j = 0; j < KPL; j++) st[lane * PAD_W + j] = outl[j];
            __syncwarp();
            float* lp = lrow + segb;
            #pragma unroll
            for (int k = 0; k < 8; k++) {
                int i = k * 32 + lane;
                __stcs(lp + i, st[(i >> 3) * PAD_W + (i & 7)]);
            }
            __syncwarp();   // staging safe for next segment
        } else {
            #pragma unroll
            for (int j = 0; j < KPL; j++) {
                if (base + j < T) { lrow[base + j] = outl[j]; srow[base + j] = outs[j]; }
            }
        }

        c_lam = __shfl_sync(FULL_MASK, xl, 0);
        c_sum = __shfl_sync(FULL_MASK, xs, 0);
    }
}

extern "C" void kernel_launch(void* const* d_in, const int* in_sizes, int n_in,
                              void* d_out, int out_size)
{
    const float* values    = (const float*)d_in[0];
    const float* rewards   = (const float*)d_in[1];
    const float* dones     = (const float*)d_in[2];
    const float* raw_gamma = (const float*)d_in[3];
    const float* raw_lambd = (const float*)d_in[4];
    const int*   p_start   = (n_in > 5) ? (const int*)d_in[5] : nullptr;

    const int T = in_sizes[4];
    const int B = in_sizes[1] / T;

    float* out_lam = (float*)d_out;                       // B*(T+1)
    float* out_sum = (float*)d_out + (size_t)B * (T + 1); // B*T

    const int threads = WPB * 32;
    const int blocks  = (B + WPB - 1) / WPB;

    td_scan_kernel<<<blocks, threads>>>(
        values, rewards, dones, raw_gamma, raw_lambd, p_start,
        out_lam, out_sum, B, T);
}